// round 3
// baseline (speedup 1.0000x reference)
#include <cuda_runtime.h>
#include <cuda_bf16.h>
#include <math.h>

#define KTOT 2048
#define NJ   40
#define NT   5            // 5 n-tiles of 8 cols
#define NKC  128          // 2048/16 k-chunks
#define KC   64
#define KCP  68
#define SMARGIN 0.31f

// Scratch
__device__ float g_Wp[KTOT * NJ];            // packed [k][40] = [W_cls | W_fl]
__device__ float g_W12[KTOT * NJ];           // fused weight (fp32, exact-ish)
__device__ float g_c[NJ];                    // fused bias
__device__ float g_cpart[8 * NJ];            // deterministic bias partials
__device__ float g_part[8 * KTOT * NJ];      // K-split partials for W12 build
__device__ uint2 g_Bfh[NKC * NT * 32];       // B fragments, bf16 hi
__device__ uint2 g_Bfl[NKC * NT * 32];       // B fragments, bf16 lo (residual)

// ---------------------------------------------------------------------------
// Pack W_cls/W_fl -> g_Wp;  init g_c with raw biases
// ---------------------------------------------------------------------------
__global__ void pack_w_kernel(const float* __restrict__ Wcls, const float* __restrict__ Wfl,
                              const float* __restrict__ bcls, const float* __restrict__ bfl) {
    int i = blockIdx.x * 256 + threadIdx.x;
    if (i < KTOT * NJ) {
        int m = i / NJ, j = i - m * NJ;
        g_Wp[i] = (j < 20) ? Wcls[m * 20 + j] : Wfl[m * 20 + (j - 20)];
    }
    if (i < NJ) g_c[i] = (i < 20) ? bcls[i] : bfl[i - 20];
}

// ---------------------------------------------------------------------------
// Bias partials: block b covers k in [b*256, b*256+256).  Coalesced row reads,
// warp butterfly per j, deterministic smem tree.  -> g_cpart[b][j]
// ---------------------------------------------------------------------------
__global__ __launch_bounds__(256)
void bias_kernel(const float* __restrict__ benc) {
    __shared__ float sw[8][NJ];
    int tid = threadIdx.x;
    int k = blockIdx.x * 256 + tid;
    int warp = tid >> 5, lane = tid & 31;
    float b = benc[k];
    const float* wr = g_Wp + (size_t)k * NJ;
    float w[NJ];
#pragma unroll
    for (int j4 = 0; j4 < NJ / 4; j4++) {
        float4 v = *(const float4*)(wr + j4 * 4);
        w[j4*4+0] = v.x; w[j4*4+1] = v.y; w[j4*4+2] = v.z; w[j4*4+3] = v.w;
    }
#pragma unroll
    for (int j = 0; j < NJ; j++) {
        float s = b * w[j];
#pragma unroll
        for (int o = 16; o > 0; o >>= 1) s += __shfl_xor_sync(0xffffffffu, s, o);
        if (lane == 0) sw[warp][j] = s;
    }
    __syncthreads();
    if (tid < NJ) {
        float t = 0.f;
#pragma unroll
        for (int p = 0; p < 8; p++) t += sw[p][tid];
        g_cpart[blockIdx.x * NJ + tid] = t;
    }
}

// ---------------------------------------------------------------------------
// fp32 skinny GEMM for phase A only: g_part[split] = W_enc @ g_Wp (K-split 8)
// ---------------------------------------------------------------------------
__global__ __launch_bounds__(256, 3)
void skinny_gemm_kernel(const float* __restrict__ A, int M) {
    const float* __restrict__ W = g_Wp;
    const int ntiles = M >> 6;
    int tile  = blockIdx.x % ntiles;
    int split = blockIdx.x / ntiles;
    const int kspan = KTOT / 8;
    int kbeg = split * kspan;

    __shared__ float xs[64 * KCP];
    __shared__ float ws[NJ * KCP];

    int tid = threadIdx.x;
    int cg = tid & 7, rg = tid >> 3;
    int j0 = cg * 5, r0 = rg * 2;

    float acc[2][5];
#pragma unroll
    for (int r = 0; r < 2; r++)
#pragma unroll
        for (int j = 0; j < 5; j++) acc[r][j] = 0.f;

    const float* Abase = A + (size_t)(tile * 64) * KTOT + kbeg;

    for (int kc = 0; kc < kspan; kc += KC) {
#pragma unroll
        for (int p = 0; p < 4; p++) {
            int idx = tid + p * 256;
            int row = idx >> 4, c4 = idx & 15;
            float4 v = *(const float4*)(Abase + (size_t)row * KTOT + kc + c4 * 4);
            *(float4*)&xs[row * KCP + c4 * 4] = v;
        }
        {
            const float* Wc = W + (size_t)(kbeg + kc) * NJ;
#pragma unroll
            for (int p = 0; p < 3; p++) {
                int idx = tid + p * 256;
                if (idx < (KC * NJ) / 4) {
                    float4 v = *(const float4*)(Wc + idx * 4);
                    float vv[4] = {v.x, v.y, v.z, v.w};
#pragma unroll
                    for (int e = 0; e < 4; e++) {
                        int el = idx * 4 + e;
                        int k = el / NJ, j = el - k * NJ;
                        ws[j * KCP + k] = vv[e];
                    }
                }
            }
        }
        __syncthreads();
#pragma unroll
        for (int k4 = 0; k4 < KC / 4; k4++) {
            float4 x0 = *(const float4*)&xs[(r0 + 0) * KCP + k4 * 4];
            float4 x1 = *(const float4*)&xs[(r0 + 1) * KCP + k4 * 4];
#pragma unroll
            for (int jj = 0; jj < 5; jj++) {
                float4 w = *(const float4*)&ws[(j0 + jj) * KCP + k4 * 4];
                acc[0][jj] += x0.x * w.x; acc[0][jj] += x0.y * w.y;
                acc[0][jj] += x0.z * w.z; acc[0][jj] += x0.w * w.w;
                acc[1][jj] += x1.x * w.x; acc[1][jj] += x1.y * w.y;
                acc[1][jj] += x1.z * w.z; acc[1][jj] += x1.w * w.w;
            }
        }
        __syncthreads();
    }

    float* o = g_part + ((size_t)split * M + tile * 64) * NJ;
#pragma unroll
    for (int r = 0; r < 2; r++)
#pragma unroll
        for (int jj = 0; jj < 5; jj++)
            o[(r0 + r) * NJ + j0 + jj] = acc[r][jj];
}

__global__ void reduce_w12_kernel() {
    int i = blockIdx.x * 256 + threadIdx.x;
    if (i < KTOT * NJ) {
        float s = 0.f;
#pragma unroll
        for (int p = 0; p < 8; p++) s += g_part[p * (KTOT * NJ) + i];
        g_W12[i] = s;
    }
}

// ---------------------------------------------------------------------------
// Build bf16 hi/lo B fragments from g_W12; also finalize g_c (deterministic)
// frag idx = (kc*5 + nt)*32 + lane ; lane holds B[k0..k0+1][n], B[k0+8..9][n]
// ---------------------------------------------------------------------------
__device__ __forceinline__ unsigned pack_bf2(float a, float b) {
    __nv_bfloat162 h = __float22bfloat162_rn(make_float2(a, b));
    return *reinterpret_cast<unsigned*>(&h);
}
__device__ __forceinline__ float bf_res(float v) {
    __nv_bfloat16 h = __float2bfloat16_rn(v);
    return v - __bfloat162float(h);
}

__global__ void bfrag_kernel() {
    int idx = blockIdx.x * 256 + threadIdx.x;
    if (idx < NJ) {                    // finalize bias
        float s = g_c[idx];
#pragma unroll
        for (int p = 0; p < 8; p++) s += g_cpart[p * NJ + idx];
        g_c[idx] = s;
    }
    if (idx >= NKC * NT * 32) return;
    int lane = idx & 31;
    int nt = (idx >> 5) % NT;
    int kc = idx / (NT * 32);
    int k0 = kc * 16 + (lane & 3) * 2;
    int n  = nt * 8 + (lane >> 2);
    float b0 = g_W12[(k0 + 0) * NJ + n];
    float b1 = g_W12[(k0 + 1) * NJ + n];
    float b2 = g_W12[(k0 + 8) * NJ + n];
    float b3 = g_W12[(k0 + 9) * NJ + n];
    g_Bfh[idx] = make_uint2(pack_bf2(b0, b1), pack_bf2(b2, b3));
    g_Bfl[idx] = make_uint2(pack_bf2(bf_res(b0), bf_res(b1)),
                            pack_bf2(bf_res(b2), bf_res(b3)));
}

// ---------------------------------------------------------------------------
// Main fused kernel: logits = x @ W12 + c via bf16-split mma.sync, then
// dual softmax + threshold + write, all in registers/warp shuffles.
// Grid: M/128 CTAs, 8 warps; warp tile = 16 rows x 40 cols.
// ---------------------------------------------------------------------------
#define MMA_BF16(d, a0, a1, a2, a3, b0, b1)                                   \
    asm volatile("mma.sync.aligned.m16n8k16.row.col.f32.bf16.bf16.f32 "       \
                 "{%0,%1,%2,%3}, {%4,%5,%6,%7}, {%8,%9}, {%0,%1,%2,%3};\n"    \
                 : "+f"(d[0]), "+f"(d[1]), "+f"(d[2]), "+f"(d[3])             \
                 : "r"(a0), "r"(a1), "r"(a2), "r"(a3), "r"(b0), "r"(b1))

__device__ __forceinline__ void cvt_split(float2 v, unsigned& h, unsigned& l) {
    __nv_bfloat162 hb = __float22bfloat162_rn(make_float2(v.x, v.y));
    float rx = v.x - __bfloat162float(hb.x);
    float ry = v.y - __bfloat162float(hb.y);
    __nv_bfloat162 lb = __float22bfloat162_rn(make_float2(rx, ry));
    h = *reinterpret_cast<unsigned*>(&hb);
    l = *reinterpret_cast<unsigned*>(&lb);
}

__global__ __launch_bounds__(256)
void mma_main_kernel(const float* __restrict__ x, float* __restrict__ out) {
    int warp = threadIdx.x >> 5, lane = threadIdx.x & 31;
    int c2 = (lane & 3) * 2;
    int row0 = blockIdx.x * 128 + warp * 16 + (lane >> 2);

    const float* A0 = x + (size_t)row0 * KTOT + c2;
    const float* A1 = A0 + (size_t)8 * KTOT;

    float acc[NT][4];
#pragma unroll
    for (int nt = 0; nt < NT; nt++) {       // init with fused bias
        float2 cb = *(const float2*)(g_c + nt * 8 + c2);
        acc[nt][0] = cb.x; acc[nt][1] = cb.y;
        acc[nt][2] = cb.x; acc[nt][3] = cb.y;
    }

    const uint2* __restrict__ Bh = g_Bfh + lane;
    const uint2* __restrict__ Bl = g_Bfl + lane;

#pragma unroll 2
    for (int kc = 0; kc < NKC; kc++) {
        float2 v00 = *(const float2*)(A0 + kc * 16);
        float2 v01 = *(const float2*)(A0 + kc * 16 + 8);
        float2 v10 = *(const float2*)(A1 + kc * 16);
        float2 v11 = *(const float2*)(A1 + kc * 16 + 8);
        unsigned ah0, ah1, ah2, ah3, al0, al1, al2, al3;
        cvt_split(v00, ah0, al0);   // {a0,a1}: row r,  k lo
        cvt_split(v10, ah1, al1);   // {a2,a3}: row r+8, k lo
        cvt_split(v01, ah2, al2);   // {a4,a5}: row r,  k hi
        cvt_split(v11, ah3, al3);   // {a6,a7}: row r+8, k hi
        const uint2* bh = Bh + kc * (NT * 32);
        const uint2* bl = Bl + kc * (NT * 32);
#pragma unroll
        for (int nt = 0; nt < NT; nt++) {
            uint2 wh = bh[nt * 32];
            uint2 wl = bl[nt * 32];
            MMA_BF16(acc[nt], ah0, ah1, ah2, ah3, wh.x, wh.y);
            MMA_BF16(acc[nt], al0, al1, al2, al3, wh.x, wh.y);
            MMA_BF16(acc[nt], ah0, ah1, ah2, ah3, wl.x, wl.y);
        }
    }

    // ---- fused epilogue: dual softmax + threshold, per row in 4-lane group ----
    float scl[2];
    float ecls[2][6];
#pragma unroll
    for (int half = 0; half < 2; half++) {
        float m1 = -1e30f, m2 = -1e30f, mn2 = 1e30f;
#pragma unroll
        for (int nt = 0; nt < NT; nt++)
#pragma unroll
            for (int e = 0; e < 2; e++) {
                int j = nt * 8 + c2 + e;
                float v = acc[nt][half * 2 + e];
                if (j < 20) m1 = fmaxf(m1, v);
                else { m2 = fmaxf(m2, v); mn2 = fminf(mn2, v); }
            }
        m1 = fmaxf(m1, __shfl_xor_sync(0xffffffffu, m1, 1));
        m1 = fmaxf(m1, __shfl_xor_sync(0xffffffffu, m1, 2));
        m2 = fmaxf(m2, __shfl_xor_sync(0xffffffffu, m2, 1));
        m2 = fmaxf(m2, __shfl_xor_sync(0xffffffffu, m2, 2));
        mn2 = fminf(mn2, __shfl_xor_sync(0xffffffffu, mn2, 1));
        mn2 = fminf(mn2, __shfl_xor_sync(0xffffffffu, mn2, 2));
        float s1 = 0.f, s2 = 0.f;
#pragma unroll
        for (int nt = 0; nt < NT; nt++)
#pragma unroll
            for (int e = 0; e < 2; e++) {
                int j = nt * 8 + c2 + e;
                float v = acc[nt][half * 2 + e];
                if (j < 20) {
                    float ex = __expf(v - m1);
                    if (nt < 3) ecls[half][nt * 2 + e] = ex;
                    s1 += ex;
                } else {
                    s2 += __expf(v - m2);
                }
            }
        s1 += __shfl_xor_sync(0xffffffffu, s1, 1);
        s1 += __shfl_xor_sync(0xffffffffu, s1, 2);
        s2 += __shfl_xor_sync(0xffffffffu, s2, 1);
        s2 += __shfl_xor_sync(0xffffffffu, s2, 2);
        float pred = 1.0f / s1;                       // max softmax prob
        float tau  = __expf(mn2 - m2) / s2;           // min flow softmax
        scl[half] = (pred >= tau + SMARGIN) ? pred : 0.0f;
    }
#pragma unroll
    for (int half = 0; half < 2; half++) {
        float* orow = out + (size_t)(row0 + half * 8) * 20;
#pragma unroll
        for (int nt = 0; nt < 3; nt++) {
            int j0 = nt * 8 + c2;
            if (j0 < 20) {
                float2 w = make_float2(ecls[half][nt * 2 + 0] * scl[half],
                                       ecls[half][nt * 2 + 1] * scl[half]);
                *(float2*)(orow + j0) = w;
            }
        }
    }
}

// ---------------------------------------------------------------------------
extern "C" void kernel_launch(void* const* d_in, const int* in_sizes, int n_in,
                              void* d_out, int out_size) {
    const float* x    = (const float*)d_in[0];
    const float* Wenc = (const float*)d_in[1];
    const float* benc = (const float*)d_in[2];
    const float* Wcls = (const float*)d_in[3];
    const float* bcls = (const float*)d_in[4];
    const float* Wfl  = (const float*)d_in[5];
    const float* bfl  = (const float*)d_in[6];
    float* out = (float*)d_out;
    int M = in_sizes[0] / KTOT;   // 16384

    pack_w_kernel<<<(KTOT * NJ + 255) / 256, 256>>>(Wcls, Wfl, bcls, bfl);
    skinny_gemm_kernel<<<(KTOT / 64) * 8, 256>>>(Wenc, KTOT);       // W12 partials
    reduce_w12_kernel<<<(KTOT * NJ + 255) / 256, 256>>>();
    bias_kernel<<<KTOT / 256, 256>>>(benc);                          // partials
    bfrag_kernel<<<(NKC * NT * 32 + 255) / 256, 256>>>();            // frags + bias final
    mma_main_kernel<<<M / 128, 256>>>(x, out);                       // the hot kernel
}

// round 5
// speedup vs baseline: 1.0505x; 1.0505x over previous
#include <cuda_runtime.h>
#include <math.h>
#include <cstdint>

#define KTOT 2048
#define NJ   40
#define KC   64
#define KCP  68
#define NBIAS 16
#define SMARGIN 0.31f

typedef unsigned long long ull;

// ---- device scratch -------------------------------------------------------
__device__ float g_Wp[KTOT * NJ];       // packed [k][40] = [W_cls | W_fl]
__device__ float g_W12[KTOT * NJ];      // fused weight, k-major [k][40]
__device__ float g_c[NJ];               // raw biases (bcls|bfl)
__device__ float g_cpart[NBIAS * NJ];   // bias partials
__device__ float g_part[8 * KTOT * NJ]; // K-split partials for W12 build

// ---- f32x2 helpers --------------------------------------------------------
__device__ __forceinline__ ull pack2(float a, float b) {
    ull r; asm("mov.b64 %0, {%1, %2};" : "=l"(r) : "f"(a), "f"(b)); return r;
}
__device__ __forceinline__ void ffma2(ull& d, ull a, ull b) {
    asm("fma.rn.f32x2 %0, %1, %2, %0;" : "+l"(d) : "l"(a), "l"(b));
}
__device__ __forceinline__ float2 unpack2(ull v) {
    float2 r; asm("mov.b64 {%0, %1}, %2;" : "=f"(r.x), "=f"(r.y) : "l"(v)); return r;
}
__device__ __forceinline__ uint32_t smem_u32(const void* p) {
    uint32_t a;
    asm("{ .reg .u64 t; cvta.to.shared.u64 t, %1; cvt.u32.u64 %0, t; }" : "=r"(a) : "l"(p));
    return a;
}

// ---- prep kernels ---------------------------------------------------------
__global__ void pack_w_kernel(const float* __restrict__ Wcls, const float* __restrict__ Wfl,
                              const float* __restrict__ bcls, const float* __restrict__ bfl) {
    int i = blockIdx.x * 256 + threadIdx.x;
    if (i < KTOT * NJ) {
        int m = i / NJ, j = i - m * NJ;
        g_Wp[i] = (j < 20) ? Wcls[m * 20 + j] : Wfl[m * 20 + (j - 20)];
    }
    if (i < NJ) g_c[i] = (i < 20) ? bcls[i] : bfl[i - 20];
}

__global__ __launch_bounds__(128)
void bias_kernel(const float* __restrict__ benc) {
    __shared__ float sw[4][NJ];
    int tid = threadIdx.x;
    int k = blockIdx.x * 128 + tid;
    int warp = tid >> 5, lane = tid & 31;
    float b = benc[k];
    const float* wr = g_Wp + (size_t)k * NJ;
    float w[NJ];
#pragma unroll
    for (int j4 = 0; j4 < NJ / 4; j4++) {
        float4 v = *(const float4*)(wr + j4 * 4);
        w[j4*4+0] = v.x; w[j4*4+1] = v.y; w[j4*4+2] = v.z; w[j4*4+3] = v.w;
    }
#pragma unroll
    for (int j = 0; j < NJ; j++) {
        float s = b * w[j];
#pragma unroll
        for (int o = 16; o > 0; o >>= 1) s += __shfl_xor_sync(0xffffffffu, s, o);
        if (lane == 0) sw[warp][j] = s;
    }
    __syncthreads();
    if (tid < NJ) {
        float t = (sw[0][tid] + sw[1][tid]) + (sw[2][tid] + sw[3][tid]);
        g_cpart[blockIdx.x * NJ + tid] = t;
    }
}

// fp32 skinny GEMM, phase A only: g_part[split] = W_enc @ g_Wp (K-split 8)
__global__ __launch_bounds__(256, 3)
void skinny_gemm_kernel(const float* __restrict__ A, int M) {
    const float* __restrict__ W = g_Wp;
    const int ntiles = M >> 6;
    int tile  = blockIdx.x % ntiles;
    int split = blockIdx.x / ntiles;
    const int kspan = KTOT / 8;
    int kbeg = split * kspan;

    __shared__ float xs[64 * KCP];
    __shared__ float ws[NJ * KCP];

    int tid = threadIdx.x;
    int cg = tid & 7, rg = tid >> 3;
    int j0 = cg * 5, r0 = rg * 2;

    float acc[2][5];
#pragma unroll
    for (int r = 0; r < 2; r++)
#pragma unroll
        for (int j = 0; j < 5; j++) acc[r][j] = 0.f;

    const float* Abase = A + (size_t)(tile * 64) * KTOT + kbeg;

    for (int kc = 0; kc < kspan; kc += KC) {
#pragma unroll
        for (int p = 0; p < 4; p++) {
            int idx = tid + p * 256;
            int row = idx >> 4, c4 = idx & 15;
            float4 v = *(const float4*)(Abase + (size_t)row * KTOT + kc + c4 * 4);
            *(float4*)&xs[row * KCP + c4 * 4] = v;
        }
        {
            const float* Wc = W + (size_t)(kbeg + kc) * NJ;
#pragma unroll
            for (int p = 0; p < 3; p++) {
                int idx = tid + p * 256;
                if (idx < (KC * NJ) / 4) {
                    float4 v = *(const float4*)(Wc + idx * 4);
                    float vv[4] = {v.x, v.y, v.z, v.w};
#pragma unroll
                    for (int e = 0; e < 4; e++) {
                        int el = idx * 4 + e;
                        int k = el / NJ, j = el - k * NJ;
                        ws[j * KCP + k] = vv[e];
                    }
                }
            }
        }
        __syncthreads();
#pragma unroll
        for (int k4 = 0; k4 < KC / 4; k4++) {
            float4 x0 = *(const float4*)&xs[(r0 + 0) * KCP + k4 * 4];
            float4 x1 = *(const float4*)&xs[(r0 + 1) * KCP + k4 * 4];
#pragma unroll
            for (int jj = 0; jj < 5; jj++) {
                float4 w = *(const float4*)&ws[(j0 + jj) * KCP + k4 * 4];
                acc[0][jj] += x0.x * w.x; acc[0][jj] += x0.y * w.y;
                acc[0][jj] += x0.z * w.z; acc[0][jj] += x0.w * w.w;
                acc[1][jj] += x1.x * w.x; acc[1][jj] += x1.y * w.y;
                acc[1][jj] += x1.z * w.z; acc[1][jj] += x1.w * w.w;
            }
        }
        __syncthreads();
    }

    float* o = g_part + ((size_t)split * M + tile * 64) * NJ;
#pragma unroll
    for (int r = 0; r < 2; r++)
#pragma unroll
        for (int jj = 0; jj < 5; jj++)
            o[(r0 + r) * NJ + j0 + jj] = acc[r][jj];
}

__global__ void reduce_w12_kernel() {
    int i = blockIdx.x * 256 + threadIdx.x;
    if (i < KTOT * NJ) {
        float s = 0.f;
#pragma unroll
        for (int p = 0; p < 8; p++) s += g_part[p * (KTOT * NJ) + i];
        g_W12[i] = s;
    }
}

// ---- main f32x2 kernel ----------------------------------------------------
// CTA: 256 threads = 4 k-splits x 64 rows. Each thread: 1 row, all 40 cols,
// 512 k. x gmem->reg; W12 chunk (4x64x40) staged in smem; inner k:
// 20 fma.rn.f32x2 + 10 ld.shared.v2.u64 + 1 pack.  Epilogue fused.
__global__ __launch_bounds__(256, 2)
void f32x2_main_kernel(const float* __restrict__ x, float* __restrict__ out) {
    __shared__ __align__(16) char smbuf[4 * 64 * 44 * 4];  // W overlay / partials
    __shared__ float cb[NJ];
    float* smW = (float*)smbuf;          // [4][64][40] floats while computing
    float* smP = (float*)smbuf;          // [4][64][44] floats for partials

    int tid = threadIdx.x;
    int split = tid >> 6;                // 0..3
    int rloc  = tid & 63;                // 0..63
    size_t row = (size_t)blockIdx.x * 64 + rloc;

    // fused bias finalize (redundant per CTA, tiny)
    if (tid < NJ) {
        float s = g_c[tid];
#pragma unroll
        for (int p = 0; p < NBIAS; p++) s += g_cpart[p * NJ + tid];
        cb[tid] = s;
    }

    ull acc[20];
#pragma unroll
    for (int p = 0; p < 20; p++) acc[p] = pack2(0.f, 0.f);

    const float* xr = x + row * KTOT + split * 512;
    uint32_t wbase = smem_u32(smW) + (uint32_t)split * (64 * 40 * 4);

    for (int kc = 0; kc < 8; kc++) {
        __syncthreads();
        // stage W chunk: [4 splits][64 k][40] floats = 2560 float4, coalesced
#pragma unroll
        for (int it = 0; it < 10; it++) {
            int q = it * 256 + tid;             // float4 index 0..2559
            int s = q / 640, off = q - s * 640;
            float4 v = *(const float4*)(g_W12 + (size_t)(s * 512 + kc * 64) * NJ + off * 4);
            ((float4*)smW)[q] = v;
        }
        __syncthreads();

        const float* xc = xr + kc * 64;
#pragma unroll
        for (int h = 0; h < 2; h++) {           // two halves of 32 k
            float4 xv[8];
#pragma unroll
            for (int i = 0; i < 8; i++)
                xv[i] = *(const float4*)(xc + h * 32 + i * 4);
#pragma unroll
            for (int e = 0; e < 32; e++) {
                float a = ((const float*)xv)[e];
                ull aa = pack2(a, a);
                uint32_t wa = wbase + (uint32_t)(h * 32 + e) * 160;
#pragma unroll
                for (int p = 0; p < 10; p++) {
                    ull w0, w1;
                    asm("ld.shared.v2.u64 {%0, %1}, [%2];"
                        : "=l"(w0), "=l"(w1) : "r"(wa + p * 16));
                    ffma2(acc[2 * p], aa, w0);
                    ffma2(acc[2 * p + 1], aa, w1);
                }
            }
        }
    }

    // write per-split partials to smem (stride 44 floats)
    __syncthreads();
    {
        float* pr = smP + (size_t)(split * 64 + rloc) * 44;
#pragma unroll
        for (int p = 0; p < 20; p++)
            *(float2*)(pr + 2 * p) = unpack2(acc[p]);
    }
    __syncthreads();

    // rows 0..63: reduce 4 splits + bias, dual softmax, threshold, write
    if (tid < 64) {
        float lg[NJ];
#pragma unroll
        for (int j4 = 0; j4 < 10; j4++) {
            float4 s0 = *(const float4*)(smP + (size_t)(0 * 64 + tid) * 44 + j4 * 4);
            float4 s1 = *(const float4*)(smP + (size_t)(1 * 64 + tid) * 44 + j4 * 4);
            float4 s2 = *(const float4*)(smP + (size_t)(2 * 64 + tid) * 44 + j4 * 4);
            float4 s3 = *(const float4*)(smP + (size_t)(3 * 64 + tid) * 44 + j4 * 4);
            lg[j4*4+0] = cb[j4*4+0] + ((s0.x + s1.x) + (s2.x + s3.x));
            lg[j4*4+1] = cb[j4*4+1] + ((s0.y + s1.y) + (s2.y + s3.y));
            lg[j4*4+2] = cb[j4*4+2] + ((s0.z + s1.z) + (s2.z + s3.z));
            lg[j4*4+3] = cb[j4*4+3] + ((s0.w + s1.w) + (s2.w + s3.w));
        }
        // cls softmax
        float m1 = lg[0];
#pragma unroll
        for (int j = 1; j < 20; j++) m1 = fmaxf(m1, lg[j]);
        float e[20], s1 = 0.f;
#pragma unroll
        for (int j = 0; j < 20; j++) { e[j] = __expf(lg[j] - m1); s1 += e[j]; }
        float pred = 1.f / s1;
        // flow softmax min -> tau
        float m2 = lg[20], mn2 = lg[20];
#pragma unroll
        for (int j = 21; j < NJ; j++) { m2 = fmaxf(m2, lg[j]); mn2 = fminf(mn2, lg[j]); }
        float s2 = 0.f;
#pragma unroll
        for (int j = 20; j < NJ; j++) s2 += __expf(lg[j] - m2);
        float tau = __expf(mn2 - m2) / s2;
        float scl = (pred >= tau + SMARGIN) ? pred : 0.f;
        float* o = out + ((size_t)blockIdx.x * 64 + tid) * 20;
#pragma unroll
        for (int j = 0; j < 10; j++)
            *(float2*)(o + j * 2) = make_float2(e[j * 2] * scl, e[j * 2 + 1] * scl);
    }
}

// ---------------------------------------------------------------------------
extern "C" void kernel_launch(void* const* d_in, const int* in_sizes, int n_in,
                              void* d_out, int out_size) {
    const float* x    = (const float*)d_in[0];
    const float* Wenc = (const float*)d_in[1];
    const float* benc = (const float*)d_in[2];
    const float* Wcls = (const float*)d_in[3];
    const float* bcls = (const float*)d_in[4];
    const float* Wfl  = (const float*)d_in[5];
    const float* bfl  = (const float*)d_in[6];
    float* out = (float*)d_out;
    int M = in_sizes[0] / KTOT;   // 16384

    pack_w_kernel<<<(KTOT * NJ + 255) / 256, 256>>>(Wcls, Wfl, bcls, bfl);
    skinny_gemm_kernel<<<(KTOT / 64) * 8, 256>>>(Wenc, KTOT);
    reduce_w12_kernel<<<(KTOT * NJ + 255) / 256, 256>>>();
    bias_kernel<<<NBIAS, 128>>>(benc);
    f32x2_main_kernel<<<M / 64, 256>>>(x, out);
}

// round 6
// speedup vs baseline: 1.3431x; 1.2785x over previous
#include <cuda_runtime.h>
#include <math.h>
#include <cstdint>

#define KTOT 2048
#define NJ   40
#define KC   64
#define KCP  68
#define NBIAS 16
#define SMARGIN 0.31f
#define BUFB 45056u          // bytes per smem buffer: x 128*68*4 + W 64*40*4

typedef unsigned long long ull;

// ---- device scratch -------------------------------------------------------
__device__ float g_Wp[KTOT * NJ];
__device__ float g_W12[KTOT * NJ];
__device__ float g_c[NJ];
__device__ float g_cpart[NBIAS * NJ];
__device__ float g_part[8 * KTOT * NJ];

// ---- helpers --------------------------------------------------------------
__device__ __forceinline__ ull pack2(float a, float b) {
    ull r; asm("mov.b64 %0, {%1, %2};" : "=l"(r) : "f"(a), "f"(b)); return r;
}
__device__ __forceinline__ void ffma2(ull& d, ull a, ull b) {
    asm("fma.rn.f32x2 %0, %1, %2, %0;" : "+l"(d) : "l"(a), "l"(b));
}
__device__ __forceinline__ float2 unpack2(ull v) {
    float2 r; asm("mov.b64 {%0, %1}, %2;" : "=f"(r.x), "=f"(r.y) : "l"(v)); return r;
}
__device__ __forceinline__ uint32_t smem_u32(const void* p) {
    uint32_t a;
    asm("{ .reg .u64 t; cvta.to.shared.u64 t, %1; cvt.u32.u64 %0, t; }" : "=r"(a) : "l"(p));
    return a;
}
__device__ __forceinline__ void cp_async16(uint32_t d, const void* s) {
    asm volatile("cp.async.cg.shared.global [%0], [%1], 16;" :: "r"(d), "l"(s));
}
__device__ __forceinline__ void cp_commit() { asm volatile("cp.async.commit_group;" ::: "memory"); }
__device__ __forceinline__ void cp_wait0()  { asm volatile("cp.async.wait_group 0;" ::: "memory"); }

// ---- prep kernels (unchanged, validated) ----------------------------------
__global__ void pack_w_kernel(const float* __restrict__ Wcls, const float* __restrict__ Wfl,
                              const float* __restrict__ bcls, const float* __restrict__ bfl) {
    int i = blockIdx.x * 256 + threadIdx.x;
    if (i < KTOT * NJ) {
        int m = i / NJ, j = i - m * NJ;
        g_Wp[i] = (j < 20) ? Wcls[m * 20 + j] : Wfl[m * 20 + (j - 20)];
    }
    if (i < NJ) g_c[i] = (i < 20) ? bcls[i] : bfl[i - 20];
}

__global__ __launch_bounds__(128)
void bias_kernel(const float* __restrict__ benc) {
    __shared__ float sw[4][NJ];
    int tid = threadIdx.x;
    int k = blockIdx.x * 128 + tid;
    int warp = tid >> 5, lane = tid & 31;
    float b = benc[k];
    const float* wr = g_Wp + (size_t)k * NJ;
    float w[NJ];
#pragma unroll
    for (int j4 = 0; j4 < NJ / 4; j4++) {
        float4 v = *(const float4*)(wr + j4 * 4);
        w[j4*4+0] = v.x; w[j4*4+1] = v.y; w[j4*4+2] = v.z; w[j4*4+3] = v.w;
    }
#pragma unroll
    for (int j = 0; j < NJ; j++) {
        float s = b * w[j];
#pragma unroll
        for (int o = 16; o > 0; o >>= 1) s += __shfl_xor_sync(0xffffffffu, s, o);
        if (lane == 0) sw[warp][j] = s;
    }
    __syncthreads();
    if (tid < NJ) {
        float t = (sw[0][tid] + sw[1][tid]) + (sw[2][tid] + sw[3][tid]);
        g_cpart[blockIdx.x * NJ + tid] = t;
    }
}

__global__ __launch_bounds__(256, 3)
void skinny_gemm_kernel(const float* __restrict__ A, int M) {
    const float* __restrict__ W = g_Wp;
    const int ntiles = M >> 6;
    int tile  = blockIdx.x % ntiles;
    int split = blockIdx.x / ntiles;
    const int kspan = KTOT / 8;
    int kbeg = split * kspan;

    __shared__ float xs[64 * KCP];
    __shared__ float ws[NJ * KCP];

    int tid = threadIdx.x;
    int cg = tid & 7, rg = tid >> 3;
    int j0 = cg * 5, r0 = rg * 2;

    float acc[2][5];
#pragma unroll
    for (int r = 0; r < 2; r++)
#pragma unroll
        for (int j = 0; j < 5; j++) acc[r][j] = 0.f;

    const float* Abase = A + (size_t)(tile * 64) * KTOT + kbeg;

    for (int kc = 0; kc < kspan; kc += KC) {
#pragma unroll
        for (int p = 0; p < 4; p++) {
            int idx = tid + p * 256;
            int row = idx >> 4, c4 = idx & 15;
            float4 v = *(const float4*)(Abase + (size_t)row * KTOT + kc + c4 * 4);
            *(float4*)&xs[row * KCP + c4 * 4] = v;
        }
        {
            const float* Wc = W + (size_t)(kbeg + kc) * NJ;
#pragma unroll
            for (int p = 0; p < 3; p++) {
                int idx = tid + p * 256;
                if (idx < (KC * NJ) / 4) {
                    float4 v = *(const float4*)(Wc + idx * 4);
                    float vv[4] = {v.x, v.y, v.z, v.w};
#pragma unroll
                    for (int e = 0; e < 4; e++) {
                        int el = idx * 4 + e;
                        int k = el / NJ, j = el - k * NJ;
                        ws[j * KCP + k] = vv[e];
                    }
                }
            }
        }
        __syncthreads();
#pragma unroll
        for (int k4 = 0; k4 < KC / 4; k4++) {
            float4 x0 = *(const float4*)&xs[(r0 + 0) * KCP + k4 * 4];
            float4 x1 = *(const float4*)&xs[(r0 + 1) * KCP + k4 * 4];
#pragma unroll
            for (int jj = 0; jj < 5; jj++) {
                float4 w = *(const float4*)&ws[(j0 + jj) * KCP + k4 * 4];
                acc[0][jj] += x0.x * w.x; acc[0][jj] += x0.y * w.y;
                acc[0][jj] += x0.z * w.z; acc[0][jj] += x0.w * w.w;
                acc[1][jj] += x1.x * w.x; acc[1][jj] += x1.y * w.y;
                acc[1][jj] += x1.z * w.z; acc[1][jj] += x1.w * w.w;
            }
        }
        __syncthreads();
    }

    float* o = g_part + ((size_t)split * M + tile * 64) * NJ;
#pragma unroll
    for (int r = 0; r < 2; r++)
#pragma unroll
        for (int jj = 0; jj < 5; jj++)
            o[(r0 + r) * NJ + j0 + jj] = acc[r][jj];
}

__global__ void reduce_w12_kernel() {
    int i = blockIdx.x * 256 + threadIdx.x;
    if (i < KTOT * NJ) {
        float s = 0.f;
#pragma unroll
        for (int p = 0; p < 8; p++) s += g_part[p * (KTOT * NJ) + i];
        g_W12[i] = s;
    }
}

// ---- main kernel ----------------------------------------------------------
// grid 128, block 128.  Warp w: rows [32w, 32w+32).  Lane: row pair
// (lane&15, +16), col half (lane>>4)*20.  acc = 20 f32x2.
// Per 64-k chunk: cp.async double-buffered staging of x[128x64] + W[64x40].
__device__ __forceinline__ void stage_chunk(uint32_t smb, int buf, int c,
                                            const float* __restrict__ x,
                                            size_t growbase, int tid) {
    uint32_t xd = smb + (uint32_t)buf * BUFB;
#pragma unroll
    for (int it = 0; it < 16; it++) {
        int q = it * 128 + tid;
        int rw = q >> 4, c4 = q & 15;
        cp_async16(xd + (uint32_t)(rw * 272 + c4 * 16),
                   x + (growbase + rw) * KTOT + c * 64 + c4 * 4);
    }
    uint32_t wd = xd + 34816u;
    const float* wsrc = g_W12 + (size_t)c * 2560;
#pragma unroll
    for (int it = 0; it < 5; it++) {
        int q = it * 128 + tid;
        cp_async16(wd + (uint32_t)q * 16, wsrc + q * 4);
    }
}

__global__ __launch_bounds__(128, 1)
void f32x2_main_kernel(const float* __restrict__ x, float* __restrict__ out) {
    extern __shared__ float sm[];
    __shared__ float cb[NJ];
    const int tid = threadIdx.x;
    const int warp = tid >> 5, lane = tid & 31;
    const int half = lane >> 4;                 // 0: cols 0-19, 1: cols 20-39
    const int rl = warp * 32 + (lane & 15);     // local row; pair row = rl+16
    const size_t growbase = (size_t)blockIdx.x * 128;

    if (tid < NJ) {
        float s = g_c[tid];
#pragma unroll
        for (int p = 0; p < NBIAS; p++) s += g_cpart[p * NJ + tid];
        cb[tid] = s;
    }

    const uint32_t smb = smem_u32(sm);
    stage_chunk(smb, 0, 0, x, growbase, tid);
    cp_commit(); cp_wait0();
    __syncthreads();

    ull acc[20];
#pragma unroll
    for (int p = 0; p < 20; p++) acc[p] = pack2(0.f, 0.f);

    for (int c = 0; c < 32; c++) {
        int buf = c & 1;
        if (c + 1 < 32) { stage_chunk(smb, buf ^ 1, c + 1, x, growbase, tid); cp_commit(); }
        uint32_t base = smb + (uint32_t)buf * BUFB;
        uint32_t xa0 = base + (uint32_t)(rl * 272);
        uint32_t xa1 = xa0 + 16 * 272;
        uint32_t wa  = base + 34816u + (uint32_t)(half * 80);
#pragma unroll 4
        for (int k = 0; k < 64; k++) {
            float a0, a1;
            asm("ld.shared.f32 %0, [%1];" : "=f"(a0) : "r"(xa0 + k * 4));
            asm("ld.shared.f32 %0, [%1];" : "=f"(a1) : "r"(xa1 + k * 4));
            ull p0 = pack2(a0, a0), p1 = pack2(a1, a1);
#pragma unroll
            for (int p = 0; p < 5; p++) {
                ull w0, w1;
                asm("ld.shared.v2.u64 {%0, %1}, [%2];"
                    : "=l"(w0), "=l"(w1) : "r"(wa + k * 160 + p * 16));
                ffma2(acc[p * 2], p0, w0);
                ffma2(acc[p * 2 + 1], p0, w1);
                ffma2(acc[10 + p * 2], p1, w0);
                ffma2(acc[10 + p * 2 + 1], p1, w1);
            }
        }
        if (c + 1 < 32) cp_wait0();
        __syncthreads();
    }

    // ---- epilogue: bias + dual softmax + threshold -----------------------
    float lg[2][20];
#pragma unroll
    for (int rr = 0; rr < 2; rr++)
#pragma unroll
        for (int j = 0; j < 10; j++) {
            float2 t = unpack2(acc[rr * 10 + j]);
            lg[rr][2 * j]     = t.x + cb[half * 20 + 2 * j];
            lg[rr][2 * j + 1] = t.y + cb[half * 20 + 2 * j + 1];
        }

    float pred[2], tauv[2] = {0.f, 0.f};
    float e[2][20];
#pragma unroll
    for (int rr = 0; rr < 2; rr++) {
        if (half == 0) {            // cls softmax
            float m1 = lg[rr][0];
#pragma unroll
            for (int j = 1; j < 20; j++) m1 = fmaxf(m1, lg[rr][j]);
            float s1 = 0.f;
#pragma unroll
            for (int j = 0; j < 20; j++) { e[rr][j] = __expf(lg[rr][j] - m1); s1 += e[rr][j]; }
            pred[rr] = 1.f / s1;
        } else {                    // flow softmax min -> tau
            float m2 = lg[rr][0], mn2 = lg[rr][0];
#pragma unroll
            for (int j = 1; j < 20; j++) { m2 = fmaxf(m2, lg[rr][j]); mn2 = fminf(mn2, lg[rr][j]); }
            float s2 = 0.f;
#pragma unroll
            for (int j = 0; j < 20; j++) s2 += __expf(lg[rr][j] - m2);
            tauv[rr] = __expf(mn2 - m2) / s2;
        }
    }
    float tau0 = __shfl_xor_sync(0xffffffffu, tauv[0], 16);
    float tau1 = __shfl_xor_sync(0xffffffffu, tauv[1], 16);
    if (half == 0) {
        float t[2] = {tau0, tau1};
#pragma unroll
        for (int rr = 0; rr < 2; rr++) {
            float scl = (pred[rr] >= t[rr] + SMARGIN) ? pred[rr] : 0.f;
            float* o = out + (growbase + rl + rr * 16) * 20;
#pragma unroll
            for (int j = 0; j < 10; j++)
                *(float2*)(o + 2 * j) = make_float2(e[rr][2 * j] * scl, e[rr][2 * j + 1] * scl);
        }
    }
}

// ---------------------------------------------------------------------------
extern "C" void kernel_launch(void* const* d_in, const int* in_sizes, int n_in,
                              void* d_out, int out_size) {
    const float* x    = (const float*)d_in[0];
    const float* Wenc = (const float*)d_in[1];
    const float* benc = (const float*)d_in[2];
    const float* Wcls = (const float*)d_in[3];
    const float* bcls = (const float*)d_in[4];
    const float* Wfl  = (const float*)d_in[5];
    const float* bfl  = (const float*)d_in[6];
    float* out = (float*)d_out;
    int M = in_sizes[0] / KTOT;   // 16384

    static int smset = 0;
    if (!smset) {
        cudaFuncSetAttribute(f32x2_main_kernel,
                             cudaFuncAttributeMaxDynamicSharedMemorySize, 2 * BUFB);
        smset = 1;
    }

    pack_w_kernel<<<(KTOT * NJ + 255) / 256, 256>>>(Wcls, Wfl, bcls, bfl);
    skinny_gemm_kernel<<<(KTOT / 64) * 8, 256>>>(Wenc, KTOT);
    reduce_w12_kernel<<<(KTOT * NJ + 255) / 256, 256>>>();
    bias_kernel<<<NBIAS, 128>>>(benc);
    f32x2_main_kernel<<<M / 128, 128, 2 * BUFB>>>(x, out);
}